// round 14
// baseline (speedup 1.0000x reference)
#include <cuda_runtime.h>
#include <math.h>

#define Hh 8
#define Dm 128
#define INSZ 512
#define OUTN 1024
#define HD 1024            // H*D rows
#define SLAB 16384         // D*D
#define SM_SZ 16777216     // H*D*D*D
#define OFF_S 512
#define OFF_SM 131584      // 512 + H*D*D

// scratch: k/q projections and per-row scalars
__device__ float g_k[HD], g_q[Dm];
__device__ float g_AL[HD], g_BA[HD], g_U[HD], g_CW[HD], g_CB[HD],
                 g_CV[HD], g_ALP[HD], g_CZ2[HD], g_y[HD];
// fine-grained readiness flags (zero-initialized; self-resetting per replay)
__device__ int g_flag[HD];     // row hi scalars ready
__device__ int g_scnt[HD];     // slab consumers done per hi (10 each)
__device__ int g_ycnt;         // rows that finished g_y
__device__ int g_yflag;        // all g_y ready
__device__ int g_wocnt;        // W_o consumers done (512)

// ---------------- kernel 1: k,q projections (warp-per-row GEMV, float4) ----
__global__ void proj_kernel(const float* __restrict__ x,
                            const float* __restrict__ Wk,
                            const float* __restrict__ Wq) {
    int warp = (blockIdx.x * blockDim.x + threadIdx.x) >> 5;
    int lane = threadIdx.x & 31;
    if (warp >= HD + Dm) return;
    const float* wr = (warp < HD) ? (Wk + (size_t)warp * INSZ)
                                  : (Wq + (size_t)(warp - HD) * INSZ);
    const float4* w4 = (const float4*)wr;
    const float4* x4 = (const float4*)x;
    float s = 0.f;
    #pragma unroll
    for (int m = lane; m < INSZ / 4; m += 32) {
        float4 a = w4[m], b = x4[m];
        s += a.x * b.x + a.y * b.y + a.z * b.z + a.w * b.w;
    }
    #pragma unroll
    for (int o = 16; o; o >>= 1) s += __shfl_down_sync(0xffffffffu, s, o);
    if (lane == 0) {
        if (warp < HD) g_k[warp] = s;
        else           g_q[warp - HD] = s;
    }
}

// ---------------- kernel 2: per-row proj(w,z,b,v) + scalars + S_new + y ----
// PDL secondary of proj: heavy loads issue before the grid sync; after
// finishing a row, thread 0 publishes a per-hi readiness flag.
__global__ void row_kernel(const float* __restrict__ x, const float* __restrict__ S,
                           const float* __restrict__ Ww, const float* __restrict__ Wz,
                           const float* __restrict__ Wb, const float* __restrict__ Wv,
                           float* __restrict__ out) {
    int hi = blockIdx.x;          // h*128 + i
    int j  = threadIdx.x;         // 0..127
    int h  = hi >> 7;
    int wq = j >> 5, lane = j & 31;
    __shared__ float red[5][4];
    __shared__ float sc[2];

    // independent loads + partial dots (no head dependency)
    float4 xv = ((const float4*)x)[j];
    size_t ro = (size_t)hi * (INSZ / 4);
    float4 aw = ((const float4*)Ww)[ro + j];
    float4 az = ((const float4*)Wz)[ro + j];
    float4 ab = ((const float4*)Wb)[ro + j];
    float4 av = ((const float4*)Wv)[ro + j];
    float pw = aw.x * xv.x + aw.y * xv.y + aw.z * xv.z + aw.w * xv.w;
    float pz = az.x * xv.x + az.y * xv.y + az.z * xv.z + az.w * xv.w;
    float pb = ab.x * xv.x + ab.y * xv.y + ab.z * xv.z + ab.w * xv.w;
    float pv = av.x * xv.x + av.y * xv.y + av.z * xv.z + av.w * xv.w;
    float Sj = S[(size_t)hi * Dm + j];

    cudaGridDependencySynchronize();   // wait for proj_kernel (g_k, g_q)

    float kj = g_k[h * Dm + j];
    float ps = Sj * kj;           // sdot partial

    #pragma unroll
    for (int o = 16; o; o >>= 1) {
        pw += __shfl_down_sync(0xffffffffu, pw, o);
        pz += __shfl_down_sync(0xffffffffu, pz, o);
        pb += __shfl_down_sync(0xffffffffu, pb, o);
        pv += __shfl_down_sync(0xffffffffu, pv, o);
        ps += __shfl_down_sync(0xffffffffu, ps, o);
    }
    if (lane == 0) {
        red[0][wq] = pw; red[1][wq] = pz; red[2][wq] = pb;
        red[3][wq] = pv; red[4][wq] = ps;
    }
    __syncthreads();

    if (j == 0) {
        float w  = red[0][0] + red[0][1] + red[0][2] + red[0][3];
        float z  = red[1][0] + red[1][1] + red[1][2] + red[1][3];
        float b  = red[2][0] + red[2][1] + red[2][2] + red[2][3];
        float vv = red[3][0] + red[3][1] + red[3][2] + red[3][3];
        float sdot = red[4][0] + red[4][1] + red[4][2] + red[4][3];
        float g  = 1.f / (1.f + expf(-w));
        float al = 1.f / (1.f + expf(-z));
        float be = 1.f / (1.f + expf(-b));
        float r_ = al * sdot;
        float u  = be * (g * vv - r_);
        g_AL[hi] = al;
        g_BA[hi] = be * al;
        g_U[hi]  = u;
        g_CW[hi] = be * g * (1.f - g) * vv;
        g_CB[hi] = be * (1.f - be) * (g * vv - r_);
        g_CV[hi] = be * g;
        float alp = al * (1.f - al);
        g_ALP[hi] = alp;
        g_CZ2[hi] = alp * be * sdot;
        sc[0] = al; sc[1] = u;
    }
    __syncthreads();

    float al = sc[0], u = sc[1];
    float Snew = al * Sj + u * kj;
    out[OFF_S + (size_t)hi * Dm + j] = Snew;

    // y[hi] = sum_j Snew * q[j]
    float yv = Snew * g_q[j];
    #pragma unroll
    for (int o = 16; o; o >>= 1) yv += __shfl_down_sync(0xffffffffu, yv, o);
    __syncthreads();
    if (lane == 0) red[0][wq] = yv;
    __syncthreads();
    if (j == 0) {
        g_y[hi] = red[0][0] + red[0][1] + red[0][2] + red[0][3];
        __threadfence();                       // publish scalars + g_y[hi]
        atomicExch(&g_flag[hi], 1);            // per-row readiness
        int c = atomicAdd(&g_ycnt, 1);
        if (c == HD - 1) atomicExch(&g_yflag, 1);  // all g_y ready
    }
}

// ---------------- kernel 3: the 670MB sensitivity update ----------------
// PDL early-launch, NO grid sync: each block spins only on its own row's
// flag (and g_yflag for the 512 W_o blocks), so slab streaming starts as
// soon as the first rows finish instead of after the whole row_kernel.
// Flags/counters self-reset for graph replay (10 consumers per hi, 512 for y).
__global__ void __launch_bounds__(256, 4) slab_kernel(
    const float* __restrict__ P0, const float* __restrict__ P1,
    const float* __restrict__ P2, const float* __restrict__ P3,
    const float* __restrict__ P4, const float* __restrict__ S,
    const float* __restrict__ Wo, const float* __restrict__ bo,
    float* __restrict__ out) {
    int bx  = blockIdx.x;         // 0..10239
    int tid = threadIdx.x;

    int half = bx & 1;
    int sb   = bx >> 1;           // slab id 0..5119
    int t    = sb >> 10;
    int hi   = sb & 1023;
    int h    = hi >> 7;
    int i    = hi & 127;
    int cq   = tid & 15;
    int part = tid >> 4;          // 0..15, owns j in [part*8, part*8+8)
    int c0   = half * 64 + cq * 4;

    const float* P = ((t == 0) ? P0 : (t == 1) ? P1 : (t == 2) ? P2 :
                      (t == 3) ? P3 : P4) + (size_t)hi * SLAB;

    // prefetch (independent of head results)
    float4 p[8];
    #pragma unroll
    for (int jj = 0; jj < 8; jj++)
        p[jj] = __ldcs((const float4*)(P + (part * 8 + jj) * 128 + c0));

    // fine-grained wait: only this row's scalars (+ g_y for W_o blocks)
    if (tid == 0) {
        while (*(volatile int*)&g_flag[hi] == 0) { __nanosleep(32); }
        if (bx < INSZ) {
            while (*(volatile int*)&g_yflag == 0) { __nanosleep(32); }
        }
        __threadfence();
    }
    __syncthreads();

    float kreg[8];
    #pragma unroll
    for (int jj = 0; jj < 8; jj++)
        kreg[jj] = __ldg(&g_k[h * 128 + part * 8 + jj]);

    float4 cp = make_float4(0.f, 0.f, 0.f, 0.f);
    #pragma unroll
    for (int jj = 0; jj < 8; jj++) {
        cp.x += kreg[jj] * p[jj].x;
        cp.y += kreg[jj] * p[jj].y;
        cp.z += kreg[jj] * p[jj].z;
        cp.w += kreg[jj] * p[jj].w;
    }

    __shared__ float4 red4[16][16];
    red4[part][cq] = cp;

    // folded output projection: out[row] = Wo[row,:] . y + bo[row]
    if (bx < INSZ && tid < 32) {
        const float4* wr = (const float4*)(Wo + (size_t)bx * OUTN);
        float s = 0.f;
        for (int m = tid; m < OUTN / 4; m += 32) {
            float4 a = wr[m];
            s += a.x * g_y[m * 4] + a.y * g_y[m * 4 + 1]
               + a.z * g_y[m * 4 + 2] + a.w * g_y[m * 4 + 3];
        }
        #pragma unroll
        for (int o = 16; o; o >>= 1) s += __shfl_down_sync(0xffffffffu, s, o);
        if (tid == 0) out[bx] = s + bo[bx];
    }

    __syncthreads();              // the only block barrier

    // self-reset bookkeeping (all consumers of a flag have passed it)
    if (tid == 0) {
        int c = atomicAdd(&g_scnt[hi], 1);
        if (c == 9) { g_scnt[hi] = 0; atomicExch(&g_flag[hi], 0); }
        if (bx < INSZ) {
            int d = atomicAdd(&g_wocnt, 1);
            if (d == INSZ - 1) {
                g_wocnt = 0; g_ycnt = 0; atomicExch(&g_yflag, 0);
            }
        }
    }

    float4 contr = make_float4(0.f, 0.f, 0.f, 0.f);
    #pragma unroll
    for (int pp = 0; pp < 16; pp++) {
        float4 r = red4[pp][cq];
        contr.x += r.x; contr.y += r.y; contr.z += r.z; contr.w += r.w;
    }

    float al = __ldg(&g_AL[hi]);
    float ba = __ldg(&g_BA[hi]);
    float* op = out + OFF_SM + (size_t)t * SM_SZ + (size_t)hi * SLAB;
    const float* Srow = S + (size_t)hi * 128;

    if (t == 4) {
        // D_k[i,j,c] = u_i*delta_{jc} - ba_i*S[i,c]*k_j ; rec term shared
        float u = __ldg(&g_U[hi]);
        float Ax = ba * (contr.x + __ldg(Srow + c0 + 0));
        float Ay = ba * (contr.y + __ldg(Srow + c0 + 1));
        float Az = ba * (contr.z + __ldg(Srow + c0 + 2));
        float Aw = ba * (contr.w + __ldg(Srow + c0 + 3));
        #pragma unroll
        for (int jj = 0; jj < 8; jj++) {
            int j = part * 8 + jj;
            float kj = kreg[jj];
            float4 v;
            v.x = al * p[jj].x - Ax * kj;
            v.y = al * p[jj].y - Ay * kj;
            v.z = al * p[jj].z - Az * kj;
            v.w = al * p[jj].w - Aw * kj;
            if (j == c0 + 0) v.x += u;
            if (j == c0 + 1) v.y += u;
            if (j == c0 + 2) v.z += u;
            if (j == c0 + 3) v.w += u;
            __stcs((float4*)(op + j * 128 + c0), v);
        }
    } else {
        // direct terms live only in column c == i
        float cfK, cfS = 0.f;
        if (t == 0)       cfK = __ldg(&g_CW[hi]);
        else if (t == 1) { cfK = -__ldg(&g_CZ2[hi]); cfS = __ldg(&g_ALP[hi]); }
        else if (t == 2)  cfK = __ldg(&g_CB[hi]);
        else              cfK = __ldg(&g_CV[hi]);
        float fx = (c0 + 0 == i) ? 1.f : 0.f;
        float fy = (c0 + 1 == i) ? 1.f : 0.f;
        float fz = (c0 + 2 == i) ? 1.f : 0.f;
        float fw = (c0 + 3 == i) ? 1.f : 0.f;
        float bcx = ba * contr.x, bcy = ba * contr.y;
        float bcz = ba * contr.z, bcw = ba * contr.w;
        #pragma unroll
        for (int jj = 0; jj < 8; jj++) {
            int j = part * 8 + jj;
            float kj = kreg[jj];
            float dterm = cfK * kj;
            if (t == 1) dterm += cfS * __ldg(Srow + j);
            float4 v;
            v.x = al * p[jj].x - bcx * kj + fx * dterm;
            v.y = al * p[jj].y - bcy * kj + fy * dterm;
            v.z = al * p[jj].z - bcz * kj + fz * dterm;
            v.w = al * p[jj].w - bcw * kj + fw * dterm;
            __stcs((float4*)(op + j * 128 + c0), v);
        }
    }
}

extern "C" void kernel_launch(void* const* d_in, const int* in_sizes, int n_in,
                              void* d_out, int out_size) {
    const float* x    = (const float*)d_in[0];
    const float* S    = (const float*)d_in[1];
    const float* sm_w = (const float*)d_in[2];
    const float* sm_z = (const float*)d_in[3];
    const float* sm_b = (const float*)d_in[4];
    const float* sm_v = (const float*)d_in[5];
    const float* sm_k = (const float*)d_in[6];
    const float* W_w  = (const float*)d_in[7];
    const float* W_z  = (const float*)d_in[8];
    const float* W_b  = (const float*)d_in[9];
    const float* W_v  = (const float*)d_in[10];
    const float* W_k  = (const float*)d_in[11];
    const float* W_q  = (const float*)d_in[12];
    const float* W_o  = (const float*)d_in[13];
    const float* b_o  = (const float*)d_in[14];
    float* out = (float*)d_out;

    proj_kernel<<<144, 256>>>(x, W_k, W_q);

    // row_kernel: PDL secondary of proj_kernel
    {
        cudaLaunchConfig_t cfg = {};
        cfg.gridDim = dim3(1024);
        cfg.blockDim = dim3(128);
        cfg.dynamicSmemBytes = 0;
        cfg.stream = 0;
        cudaLaunchAttribute attr[1];
        attr[0].id = cudaLaunchAttributeProgrammaticStreamSerialization;
        attr[0].val.programmaticStreamSerializationAllowed = 1;
        cfg.attrs = attr;
        cfg.numAttrs = 1;
        cudaLaunchKernelEx(&cfg, row_kernel, x, S, W_w, W_z, W_b, W_v, out);
    }

    // slab_kernel: PDL early-launch; synchronizes via per-row flags instead
    // of a grid-wide dependency sync.
    {
        cudaLaunchConfig_t cfg = {};
        cfg.gridDim = dim3(10240);
        cfg.blockDim = dim3(256);
        cfg.dynamicSmemBytes = 0;
        cfg.stream = 0;
        cudaLaunchAttribute attr[1];
        attr[0].id = cudaLaunchAttributeProgrammaticStreamSerialization;
        attr[0].val.programmaticStreamSerializationAllowed = 1;
        cfg.attrs = attr;
        cfg.numAttrs = 1;
        cudaLaunchKernelEx(&cfg, slab_kernel, sm_w, sm_z, sm_b, sm_v, sm_k,
                           S, W_o, b_o, out);
    }
}

// round 15
// speedup vs baseline: 1.0608x; 1.0608x over previous
#include <cuda_runtime.h>
#include <math.h>

#define Hh 8
#define Dm 128
#define INSZ 512
#define OUTN 1024
#define HD 1024            // H*D rows
#define SLAB 16384         // D*D
#define SM_SZ 16777216     // H*D*D*D
#define OFF_S 512
#define OFF_SM 131584      // 512 + H*D*D
#define TOT_UNITS 10240    // 5120 slabs x 2 halves
#define PGRID 592          // 148 SMs x 4 resident CTAs

// scratch: k/q projections and per-row scalars
__device__ float g_k[HD], g_q[Dm];
__device__ float g_AL[HD], g_BA[HD], g_U[HD], g_CW[HD], g_CB[HD],
                 g_CV[HD], g_ALP[HD], g_CZ2[HD], g_y[HD];

// ---------------- kernel 1: k,q projections (warp-per-row GEMV, float4) ----
__global__ void proj_kernel(const float* __restrict__ x,
                            const float* __restrict__ Wk,
                            const float* __restrict__ Wq) {
    int warp = (blockIdx.x * blockDim.x + threadIdx.x) >> 5;
    int lane = threadIdx.x & 31;
    if (warp >= HD + Dm) return;
    const float* wr = (warp < HD) ? (Wk + (size_t)warp * INSZ)
                                  : (Wq + (size_t)(warp - HD) * INSZ);
    const float4* w4 = (const float4*)wr;
    const float4* x4 = (const float4*)x;
    float s = 0.f;
    #pragma unroll
    for (int m = lane; m < INSZ / 4; m += 32) {
        float4 a = w4[m], b = x4[m];
        s += a.x * b.x + a.y * b.y + a.z * b.z + a.w * b.w;
    }
    #pragma unroll
    for (int o = 16; o; o >>= 1) s += __shfl_down_sync(0xffffffffu, s, o);
    if (lane == 0) {
        if (warp < HD) g_k[warp] = s;
        else           g_q[warp - HD] = s;
    }
}

// ---------------- kernel 2: per-row proj(w,z,b,v) + scalars + S_new + y ----
// PDL secondary: all W/x/S loads issue BEFORE cudaGridDependencySynchronize();
// only k/q consumption waits for proj_kernel.
__global__ void row_kernel(const float* __restrict__ x, const float* __restrict__ S,
                           const float* __restrict__ Ww, const float* __restrict__ Wz,
                           const float* __restrict__ Wb, const float* __restrict__ Wv,
                           float* __restrict__ out) {
    int hi = blockIdx.x;          // h*128 + i
    int j  = threadIdx.x;         // 0..127
    int h  = hi >> 7;
    int wq = j >> 5, lane = j & 31;
    __shared__ float red[5][4];
    __shared__ float sc[2];

    // independent loads + partial dots (no head dependency)
    float4 xv = ((const float4*)x)[j];
    size_t ro = (size_t)hi * (INSZ / 4);
    float4 aw = ((const float4*)Ww)[ro + j];
    float4 az = ((const float4*)Wz)[ro + j];
    float4 ab = ((const float4*)Wb)[ro + j];
    float4 av = ((const float4*)Wv)[ro + j];
    float pw = aw.x * xv.x + aw.y * xv.y + aw.z * xv.z + aw.w * xv.w;
    float pz = az.x * xv.x + az.y * xv.y + az.z * xv.z + az.w * xv.w;
    float pb = ab.x * xv.x + ab.y * xv.y + ab.z * xv.z + ab.w * xv.w;
    float pv = av.x * xv.x + av.y * xv.y + av.z * xv.z + av.w * xv.w;
    float Sj = S[(size_t)hi * Dm + j];

    cudaGridDependencySynchronize();   // wait for proj_kernel (g_k, g_q)

    float kj = g_k[h * Dm + j];
    float ps = Sj * kj;           // sdot partial

    #pragma unroll
    for (int o = 16; o; o >>= 1) {
        pw += __shfl_down_sync(0xffffffffu, pw, o);
        pz += __shfl_down_sync(0xffffffffu, pz, o);
        pb += __shfl_down_sync(0xffffffffu, pb, o);
        pv += __shfl_down_sync(0xffffffffu, pv, o);
        ps += __shfl_down_sync(0xffffffffu, ps, o);
    }
    if (lane == 0) {
        red[0][wq] = pw; red[1][wq] = pz; red[2][wq] = pb;
        red[3][wq] = pv; red[4][wq] = ps;
    }
    __syncthreads();

    if (j == 0) {
        float w  = red[0][0] + red[0][1] + red[0][2] + red[0][3];
        float z  = red[1][0] + red[1][1] + red[1][2] + red[1][3];
        float b  = red[2][0] + red[2][1] + red[2][2] + red[2][3];
        float vv = red[3][0] + red[3][1] + red[3][2] + red[3][3];
        float sdot = red[4][0] + red[4][1] + red[4][2] + red[4][3];
        float g  = 1.f / (1.f + expf(-w));
        float al = 1.f / (1.f + expf(-z));
        float be = 1.f / (1.f + expf(-b));
        float r_ = al * sdot;
        float u  = be * (g * vv - r_);
        g_AL[hi] = al;
        g_BA[hi] = be * al;
        g_U[hi]  = u;
        g_CW[hi] = be * g * (1.f - g) * vv;
        g_CB[hi] = be * (1.f - be) * (g * vv - r_);
        g_CV[hi] = be * g;
        float alp = al * (1.f - al);
        g_ALP[hi] = alp;
        g_CZ2[hi] = alp * be * sdot;
        sc[0] = al; sc[1] = u;
    }
    __syncthreads();

    float al = sc[0], u = sc[1];
    float Snew = al * Sj + u * kj;
    out[OFF_S + (size_t)hi * Dm + j] = Snew;

    // y[hi] = sum_j Snew * q[j]
    float yv = Snew * g_q[j];
    #pragma unroll
    for (int o = 16; o; o >>= 1) yv += __shfl_down_sync(0xffffffffu, yv, o);
    __syncthreads();
    if (lane == 0) red[0][wq] = yv;
    __syncthreads();
    if (j == 0) g_y[hi] = red[0][0] + red[0][1] + red[0][2] + red[0][3];
}

// ---------------- kernel 3: persistent 670MB sensitivity update ------------
// 592 persistent CTAs (4/SM), block-stride loop over the 10240 half-slab
// units. Double-buffered reduction smem -> ONE __syncthreads per unit; next
// unit's 8 LDG.128 issue right after this unit's stores, with no CTA
// teardown/dispatch in between. PDL: first unit's loads issue before the
// grid dependency sync. Units 0..511 also do one row of y @ W_o^T + b_o.
__global__ void __launch_bounds__(256, 4) slab_kernel(
    const float* __restrict__ P0, const float* __restrict__ P1,
    const float* __restrict__ P2, const float* __restrict__ P3,
    const float* __restrict__ P4, const float* __restrict__ S,
    const float* __restrict__ Wo, const float* __restrict__ bo,
    float* __restrict__ out) {
    int tid  = threadIdx.x;
    int cq   = tid & 15;
    int part = tid >> 4;          // 0..15, owns j in [part*8, part*8+8)

    __shared__ float4 red4[2][16][16];
    int par = 0;

    int u = blockIdx.x;           // current half-slab unit

    // prefetch unit u before the dependency sync (overlaps row_kernel)
    float4 p[8];
    {
        int half = u & 1, sb = u >> 1;
        int t = sb >> 10, hi = sb & 1023;
        int c0 = half * 64 + cq * 4;
        const float* P = ((t == 0) ? P0 : (t == 1) ? P1 : (t == 2) ? P2 :
                          (t == 3) ? P3 : P4) + (size_t)hi * SLAB;
        #pragma unroll
        for (int jj = 0; jj < 8; jj++)
            p[jj] = __ldcs((const float4*)(P + (part * 8 + jj) * 128 + c0));
    }

    cudaGridDependencySynchronize();   // wait for row_kernel scalars/g_y

    while (true) {
        int half = u & 1, sb = u >> 1;
        int t = sb >> 10, hi = sb & 1023;
        int h = hi >> 7, i = hi & 127;
        int c0 = half * 64 + cq * 4;

        float kreg[8];
        #pragma unroll
        for (int jj = 0; jj < 8; jj++)
            kreg[jj] = __ldg(&g_k[h * 128 + part * 8 + jj]);

        float4 cp = make_float4(0.f, 0.f, 0.f, 0.f);
        #pragma unroll
        for (int jj = 0; jj < 8; jj++) {
            cp.x += kreg[jj] * p[jj].x;
            cp.y += kreg[jj] * p[jj].y;
            cp.z += kreg[jj] * p[jj].z;
            cp.w += kreg[jj] * p[jj].w;
        }
        red4[par][part][cq] = cp;

        // folded output projection (u < 512 happens only on first iteration)
        if (u < INSZ && tid < 32) {
            const float4* wr = (const float4*)(Wo + (size_t)u * OUTN);
            float s = 0.f;
            for (int m = tid; m < OUTN / 4; m += 32) {
                float4 a = wr[m];
                s += a.x * g_y[m * 4] + a.y * g_y[m * 4 + 1]
                   + a.z * g_y[m * 4 + 2] + a.w * g_y[m * 4 + 3];
            }
            #pragma unroll
            for (int o = 16; o; o >>= 1) s += __shfl_down_sync(0xffffffffu, s, o);
            if (tid == 0) out[u] = s + bo[u];
        }

        __syncthreads();          // one barrier per unit (double-buffered smem)

        float4 contr = make_float4(0.f, 0.f, 0.f, 0.f);
        #pragma unroll
        for (int pp = 0; pp < 16; pp++) {
            float4 r = red4[par][pp][cq];
            contr.x += r.x; contr.y += r.y; contr.z += r.z; contr.w += r.w;
        }

        float al = __ldg(&g_AL[hi]);
        float ba = __ldg(&g_BA[hi]);
        float* op = out + OFF_SM + (size_t)t * SM_SZ + (size_t)hi * SLAB;
        const float* Srow = S + (size_t)hi * 128;

        if (t == 4) {
            // D_k[i,j,c] = u_i*delta_{jc} - ba_i*S[i,c]*k_j
            float uu = __ldg(&g_U[hi]);
            float Ax = ba * (contr.x + __ldg(Srow + c0 + 0));
            float Ay = ba * (contr.y + __ldg(Srow + c0 + 1));
            float Az = ba * (contr.z + __ldg(Srow + c0 + 2));
            float Aw = ba * (contr.w + __ldg(Srow + c0 + 3));
            #pragma unroll
            for (int jj = 0; jj < 8; jj++) {
                int j = part * 8 + jj;
                float kj = kreg[jj];
                float4 v;
                v.x = al * p[jj].x - Ax * kj;
                v.y = al * p[jj].y - Ay * kj;
                v.z = al * p[jj].z - Az * kj;
                v.w = al * p[jj].w - Aw * kj;
                if (j == c0 + 0) v.x += uu;
                if (j == c0 + 1) v.y += uu;
                if (j == c0 + 2) v.z += uu;
                if (j == c0 + 3) v.w += uu;
                __stcs((float4*)(op + j * 128 + c0), v);
            }
        } else {
            // direct terms live only in column c == i
            float cfK, cfS = 0.f;
            if (t == 0)       cfK = __ldg(&g_CW[hi]);
            else if (t == 1) { cfK = -__ldg(&g_CZ2[hi]); cfS = __ldg(&g_ALP[hi]); }
            else if (t == 2)  cfK = __ldg(&g_CB[hi]);
            else              cfK = __ldg(&g_CV[hi]);
            float fx = (c0 + 0 == i) ? 1.f : 0.f;
            float fy = (c0 + 1 == i) ? 1.f : 0.f;
            float fz = (c0 + 2 == i) ? 1.f : 0.f;
            float fw = (c0 + 3 == i) ? 1.f : 0.f;
            float bcx = ba * contr.x, bcy = ba * contr.y;
            float bcz = ba * contr.z, bcw = ba * contr.w;
            #pragma unroll
            for (int jj = 0; jj < 8; jj++) {
                int j = part * 8 + jj;
                float kj = kreg[jj];
                float dterm = cfK * kj;
                if (t == 1) dterm += cfS * __ldg(Srow + j);
                float4 v;
                v.x = al * p[jj].x - bcx * kj + fx * dterm;
                v.y = al * p[jj].y - bcy * kj + fy * dterm;
                v.z = al * p[jj].z - bcz * kj + fz * dterm;
                v.w = al * p[jj].w - bcw * kj + fw * dterm;
                __stcs((float4*)(op + j * 128 + c0), v);
            }
        }

        u += PGRID;
        if (u >= TOT_UNITS) break;

        // issue next unit's loads immediately (no CTA teardown in between)
        {
            int halfn = u & 1, sbn = u >> 1;
            int tn = sbn >> 10, hin = sbn & 1023;
            int c0n = halfn * 64 + cq * 4;
            const float* Pn = ((tn == 0) ? P0 : (tn == 1) ? P1 : (tn == 2) ? P2 :
                               (tn == 3) ? P3 : P4) + (size_t)hin * SLAB;
            #pragma unroll
            for (int jj = 0; jj < 8; jj++)
                p[jj] = __ldcs((const float4*)(Pn + (part * 8 + jj) * 128 + c0n));
        }
        par ^= 1;
    }
}

extern "C" void kernel_launch(void* const* d_in, const int* in_sizes, int n_in,
                              void* d_out, int out_size) {
    const float* x    = (const float*)d_in[0];
    const float* S    = (const float*)d_in[1];
    const float* sm_w = (const float*)d_in[2];
    const float* sm_z = (const float*)d_in[3];
    const float* sm_b = (const float*)d_in[4];
    const float* sm_v = (const float*)d_in[5];
    const float* sm_k = (const float*)d_in[6];
    const float* W_w  = (const float*)d_in[7];
    const float* W_z  = (const float*)d_in[8];
    const float* W_b  = (const float*)d_in[9];
    const float* W_v  = (const float*)d_in[10];
    const float* W_k  = (const float*)d_in[11];
    const float* W_q  = (const float*)d_in[12];
    const float* W_o  = (const float*)d_in[13];
    const float* b_o  = (const float*)d_in[14];
    float* out = (float*)d_out;

    proj_kernel<<<144, 256>>>(x, W_k, W_q);

    // row_kernel: PDL secondary of proj_kernel
    {
        cudaLaunchConfig_t cfg = {};
        cfg.gridDim = dim3(1024);
        cfg.blockDim = dim3(128);
        cfg.dynamicSmemBytes = 0;
        cfg.stream = 0;
        cudaLaunchAttribute attr[1];
        attr[0].id = cudaLaunchAttributeProgrammaticStreamSerialization;
        attr[0].val.programmaticStreamSerializationAllowed = 1;
        cfg.attrs = attr;
        cfg.numAttrs = 1;
        cudaLaunchKernelEx(&cfg, row_kernel, x, S, W_w, W_z, W_b, W_v, out);
    }

    // slab_kernel: persistent grid, PDL secondary of row_kernel
    {
        cudaLaunchConfig_t cfg = {};
        cfg.gridDim = dim3(PGRID);
        cfg.blockDim = dim3(256);
        cfg.dynamicSmemBytes = 0;
        cfg.stream = 0;
        cudaLaunchAttribute attr[1];
        attr[0].id = cudaLaunchAttributeProgrammaticStreamSerialization;
        attr[0].val.programmaticStreamSerializationAllowed = 1;
        cfg.attrs = attr;
        cfg.numAttrs = 1;
        cudaLaunchKernelEx(&cfg, slab_kernel, sm_w, sm_z, sm_b, sm_v, sm_k,
                           S, W_o, b_o, out);
    }
}

// round 16
// speedup vs baseline: 1.1652x; 1.0984x over previous
#include <cuda_runtime.h>
#include <math.h>

#define Hh 8
#define Dm 128
#define INSZ 512
#define OUTN 1024
#define HD 1024            // H*D rows
#define SLAB 16384         // D*D
#define SM_SZ 16777216     // H*D*D*D
#define OFF_S 512
#define OFF_SM 131584      // 512 + H*D*D

// scratch: k/q projections and per-row scalars
__device__ float g_k[HD], g_q[Dm];
__device__ float g_AL[HD], g_BA[HD], g_U[HD], g_CW[HD], g_CB[HD],
                 g_CV[HD], g_ALP[HD], g_CZ2[HD], g_y[HD];

// ---------------- kernel 1: k,q projections (warp-per-row GEMV, float4) ----
// Triggers programmatic launch completion at entry so row_kernel launches
// (and prefetches) while proj is still running.
__global__ void proj_kernel(const float* __restrict__ x,
                            const float* __restrict__ Wk,
                            const float* __restrict__ Wq) {
    cudaTriggerProgrammaticLaunchCompletion();
    int warp = (blockIdx.x * blockDim.x + threadIdx.x) >> 5;
    int lane = threadIdx.x & 31;
    if (warp >= HD + Dm) return;
    const float* wr = (warp < HD) ? (Wk + (size_t)warp * INSZ)
                                  : (Wq + (size_t)(warp - HD) * INSZ);
    const float4* w4 = (const float4*)wr;
    const float4* x4 = (const float4*)x;
    float s = 0.f;
    #pragma unroll
    for (int m = lane; m < INSZ / 4; m += 32) {
        float4 a = w4[m], b = x4[m];
        s += a.x * b.x + a.y * b.y + a.z * b.z + a.w * b.w;
    }
    #pragma unroll
    for (int o = 16; o; o >>= 1) s += __shfl_down_sync(0xffffffffu, s, o);
    if (lane == 0) {
        if (warp < HD) g_k[warp] = s;
        else           g_q[warp - HD] = s;
    }
}

// ---------------- kernel 2: per-row proj(w,z,b,v) + scalars + S_new + y ----
// PDL secondary of proj: heavy W/x/S loads issue BEFORE the grid sync.
// Triggers at entry so slab_kernel launches (and prefetches) early.
__global__ void row_kernel(const float* __restrict__ x, const float* __restrict__ S,
                           const float* __restrict__ Ww, const float* __restrict__ Wz,
                           const float* __restrict__ Wb, const float* __restrict__ Wv,
                           float* __restrict__ out) {
    cudaTriggerProgrammaticLaunchCompletion();
    int hi = blockIdx.x;          // h*128 + i
    int j  = threadIdx.x;         // 0..127
    int h  = hi >> 7;
    int wq = j >> 5, lane = j & 31;
    __shared__ float red[5][4];
    __shared__ float sc[2];

    // independent loads + partial dots (no head dependency)
    float4 xv = ((const float4*)x)[j];
    size_t ro = (size_t)hi * (INSZ / 4);
    float4 aw = ((const float4*)Ww)[ro + j];
    float4 az = ((const float4*)Wz)[ro + j];
    float4 ab = ((const float4*)Wb)[ro + j];
    float4 av = ((const float4*)Wv)[ro + j];
    float pw = aw.x * xv.x + aw.y * xv.y + aw.z * xv.z + aw.w * xv.w;
    float pz = az.x * xv.x + az.y * xv.y + az.z * xv.z + az.w * xv.w;
    float pb = ab.x * xv.x + ab.y * xv.y + ab.z * xv.z + ab.w * xv.w;
    float pv = av.x * xv.x + av.y * xv.y + av.z * xv.z + av.w * xv.w;
    float Sj = S[(size_t)hi * Dm + j];

    cudaGridDependencySynchronize();   // wait for proj_kernel (g_k, g_q)

    float kj = g_k[h * Dm + j];
    float ps = Sj * kj;           // sdot partial

    #pragma unroll
    for (int o = 16; o; o >>= 1) {
        pw += __shfl_down_sync(0xffffffffu, pw, o);
        pz += __shfl_down_sync(0xffffffffu, pz, o);
        pb += __shfl_down_sync(0xffffffffu, pb, o);
        pv += __shfl_down_sync(0xffffffffu, pv, o);
        ps += __shfl_down_sync(0xffffffffu, ps, o);
    }
    if (lane == 0) {
        red[0][wq] = pw; red[1][wq] = pz; red[2][wq] = pb;
        red[3][wq] = pv; red[4][wq] = ps;
    }
    __syncthreads();

    if (j == 0) {
        float w  = red[0][0] + red[0][1] + red[0][2] + red[0][3];
        float z  = red[1][0] + red[1][1] + red[1][2] + red[1][3];
        float b  = red[2][0] + red[2][1] + red[2][2] + red[2][3];
        float vv = red[3][0] + red[3][1] + red[3][2] + red[3][3];
        float sdot = red[4][0] + red[4][1] + red[4][2] + red[4][3];
        float g  = 1.f / (1.f + expf(-w));
        float al = 1.f / (1.f + expf(-z));
        float be = 1.f / (1.f + expf(-b));
        float r_ = al * sdot;
        float u  = be * (g * vv - r_);
        g_AL[hi] = al;
        g_BA[hi] = be * al;
        g_U[hi]  = u;
        g_CW[hi] = be * g * (1.f - g) * vv;
        g_CB[hi] = be * (1.f - be) * (g * vv - r_);
        g_CV[hi] = be * g;
        float alp = al * (1.f - al);
        g_ALP[hi] = alp;
        g_CZ2[hi] = alp * be * sdot;
        sc[0] = al; sc[1] = u;
    }
    __syncthreads();

    float al = sc[0], u = sc[1];
    float Snew = al * Sj + u * kj;
    out[OFF_S + (size_t)hi * Dm + j] = Snew;

    // y[hi] = sum_j Snew * q[j]
    float yv = Snew * g_q[j];
    #pragma unroll
    for (int o = 16; o; o >>= 1) yv += __shfl_down_sync(0xffffffffu, yv, o);
    __syncthreads();
    if (lane == 0) red[0][wq] = yv;
    __syncthreads();
    if (j == 0) g_y[hi] = red[0][0] + red[0][1] + red[0][2] + red[0][3];
}

// ---------------- kernel 3: the 670MB sensitivity update ----------------
// Two blocks per (t,h,i) slab; 256 threads, occ 4 (measured optimum).
// Thread (part 0..15, cq 0..15): 8 j-rows x 4 contiguous cols as float4.
// PDL secondary: the 8 LDG.128 prefetch issues BEFORE the dependency sync.
// First 512 blocks also compute one row of y @ W_o^T + b_o.
__global__ void __launch_bounds__(256, 4) slab_kernel(
    const float* __restrict__ P0, const float* __restrict__ P1,
    const float* __restrict__ P2, const float* __restrict__ P3,
    const float* __restrict__ P4, const float* __restrict__ S,
    const float* __restrict__ Wo, const float* __restrict__ bo,
    float* __restrict__ out) {
    int bx  = blockIdx.x;         // 0..10239
    int tid = threadIdx.x;

    int half = bx & 1;
    int sb   = bx >> 1;           // slab id 0..5119
    int t    = sb >> 10;
    int hi   = sb & 1023;
    int h    = hi >> 7;
    int i    = hi & 127;
    int cq   = tid & 15;
    int part = tid >> 4;          // 0..15, owns j in [part*8, part*8+8)
    int c0   = half * 64 + cq * 4;

    const float* P = ((t == 0) ? P0 : (t == 1) ? P1 : (t == 2) ? P2 :
                      (t == 3) ? P3 : P4) + (size_t)hi * SLAB;

    // prefetch (independent of head results)
    float4 p[8];
    #pragma unroll
    for (int jj = 0; jj < 8; jj++)
        p[jj] = __ldcs((const float4*)(P + (part * 8 + jj) * 128 + c0));

    cudaGridDependencySynchronize();   // wait for row_kernel scalars/g_y

    float kreg[8];
    #pragma unroll
    for (int jj = 0; jj < 8; jj++)
        kreg[jj] = __ldg(&g_k[h * 128 + part * 8 + jj]);

    float4 cp = make_float4(0.f, 0.f, 0.f, 0.f);
    #pragma unroll
    for (int jj = 0; jj < 8; jj++) {
        cp.x += kreg[jj] * p[jj].x;
        cp.y += kreg[jj] * p[jj].y;
        cp.z += kreg[jj] * p[jj].z;
        cp.w += kreg[jj] * p[jj].w;
    }

    __shared__ float4 red4[16][16];
    red4[part][cq] = cp;

    // folded output projection: out[row] = Wo[row,:] . y + bo[row]
    if (bx < INSZ && tid < 32) {
        const float4* wr = (const float4*)(Wo + (size_t)bx * OUTN);
        float s = 0.f;
        for (int m = tid; m < OUTN / 4; m += 32) {
            float4 a = wr[m];
            s += a.x * g_y[m * 4] + a.y * g_y[m * 4 + 1]
               + a.z * g_y[m * 4 + 2] + a.w * g_y[m * 4 + 3];
        }
        #pragma unroll
        for (int o = 16; o; o >>= 1) s += __shfl_down_sync(0xffffffffu, s, o);
        if (tid == 0) out[bx] = s + bo[bx];
    }

    __syncthreads();              // the only block barrier

    float4 contr = make_float4(0.f, 0.f, 0.f, 0.f);
    #pragma unroll
    for (int pp = 0; pp < 16; pp++) {
        float4 r = red4[pp][cq];
        contr.x += r.x; contr.y += r.y; contr.z += r.z; contr.w += r.w;
    }

    float al = __ldg(&g_AL[hi]);
    float ba = __ldg(&g_BA[hi]);
    float* op = out + OFF_SM + (size_t)t * SM_SZ + (size_t)hi * SLAB;
    const float* Srow = S + (size_t)hi * 128;

    if (t == 4) {
        // D_k[i,j,c] = u_i*delta_{jc} - ba_i*S[i,c]*k_j ; rec term shared
        float u = __ldg(&g_U[hi]);
        float Ax = ba * (contr.x + __ldg(Srow + c0 + 0));
        float Ay = ba * (contr.y + __ldg(Srow + c0 + 1));
        float Az = ba * (contr.z + __ldg(Srow + c0 + 2));
        float Aw = ba * (contr.w + __ldg(Srow + c0 + 3));
        #pragma unroll
        for (int jj = 0; jj < 8; jj++) {
            int j = part * 8 + jj;
            float kj = kreg[jj];
            float4 v;
            v.x = al * p[jj].x - Ax * kj;
            v.y = al * p[jj].y - Ay * kj;
            v.z = al * p[jj].z - Az * kj;
            v.w = al * p[jj].w - Aw * kj;
            if (j == c0 + 0) v.x += u;
            if (j == c0 + 1) v.y += u;
            if (j == c0 + 2) v.z += u;
            if (j == c0 + 3) v.w += u;
            __stcs((float4*)(op + j * 128 + c0), v);
        }
    } else {
        // direct terms live only in column c == i
        float cfK, cfS = 0.f;
        if (t == 0)       cfK = __ldg(&g_CW[hi]);
        else if (t == 1) { cfK = -__ldg(&g_CZ2[hi]); cfS = __ldg(&g_ALP[hi]); }
        else if (t == 2)  cfK = __ldg(&g_CB[hi]);
        else              cfK = __ldg(&g_CV[hi]);
        float fx = (c0 + 0 == i) ? 1.f : 0.f;
        float fy = (c0 + 1 == i) ? 1.f : 0.f;
        float fz = (c0 + 2 == i) ? 1.f : 0.f;
        float fw = (c0 + 3 == i) ? 1.f : 0.f;
        float bcx = ba * contr.x, bcy = ba * contr.y;
        float bcz = ba * contr.z, bcw = ba * contr.w;
        #pragma unroll
        for (int jj = 0; jj < 8; jj++) {
            int j = part * 8 + jj;
            float kj = kreg[jj];
            float dterm = cfK * kj;
            if (t == 1) dterm += cfS * __ldg(Srow + j);
            float4 v;
            v.x = al * p[jj].x - bcx * kj + fx * dterm;
            v.y = al * p[jj].y - bcy * kj + fy * dterm;
            v.z = al * p[jj].z - bcz * kj + fz * dterm;
            v.w = al * p[jj].w - bcw * kj + fw * dterm;
            __stcs((float4*)(op + j * 128 + c0), v);
        }
    }
}

extern "C" void kernel_launch(void* const* d_in, const int* in_sizes, int n_in,
                              void* d_out, int out_size) {
    const float* x    = (const float*)d_in[0];
    const float* S    = (const float*)d_in[1];
    const float* sm_w = (const float*)d_in[2];
    const float* sm_z = (const float*)d_in[3];
    const float* sm_b = (const float*)d_in[4];
    const float* sm_v = (const float*)d_in[5];
    const float* sm_k = (const float*)d_in[6];
    const float* W_w  = (const float*)d_in[7];
    const float* W_z  = (const float*)d_in[8];
    const float* W_b  = (const float*)d_in[9];
    const float* W_v  = (const float*)d_in[10];
    const float* W_k  = (const float*)d_in[11];
    const float* W_q  = (const float*)d_in[12];
    const float* W_o  = (const float*)d_in[13];
    const float* b_o  = (const float*)d_in[14];
    float* out = (float*)d_out;

    proj_kernel<<<144, 256>>>(x, W_k, W_q);

    // row_kernel: PDL secondary of proj_kernel
    {
        cudaLaunchConfig_t cfg = {};
        cfg.gridDim = dim3(1024);
        cfg.blockDim = dim3(128);
        cfg.dynamicSmemBytes = 0;
        cfg.stream = 0;
        cudaLaunchAttribute attr[1];
        attr[0].id = cudaLaunchAttributeProgrammaticStreamSerialization;
        attr[0].val.programmaticStreamSerializationAllowed = 1;
        cfg.attrs = attr;
        cfg.numAttrs = 1;
        cudaLaunchKernelEx(&cfg, row_kernel, x, S, W_w, W_z, W_b, W_v, out);
    }

    // slab_kernel: PDL secondary of row_kernel
    {
        cudaLaunchConfig_t cfg = {};
        cfg.gridDim = dim3(10240);
        cfg.blockDim = dim3(256);
        cfg.dynamicSmemBytes = 0;
        cfg.stream = 0;
        cudaLaunchAttribute attr[1];
        attr[0].id = cudaLaunchAttributeProgrammaticStreamSerialization;
        attr[0].val.programmaticStreamSerializationAllowed = 1;
        cfg.attrs = attr;
        cfg.numAttrs = 1;
        cudaLaunchKernelEx(&cfg, slab_kernel, sm_w, sm_z, sm_b, sm_v, sm_k,
                           S, W_o, b_o, out);
    }
}